// round 15
// baseline (speedup 1.0000x reference)
#include <cuda_runtime.h>
#include <math.h>

#define DIM 256
#define NHEAD 8
#define HD 32
#define BATCH 2
#define ND 2048
#define NOC 2048
#define ROWS (BATCH*ND)          // 4096
#define EPSF 1e-5f
#define LAMBDA_INIT 0.1f
#define SCALEF 0.17677669529663687f   // 32^-0.5

// ---------------- scratch (static __device__, no allocations) ----------------
__device__ float g_x[ROWS*DIM];        // LN1(drift)
__device__ float g_Q[ROWS*2*DIM];      // x @ Wq^T   [4096,512]
__device__ float g_K[ROWS*2*DIM];      // ocean @ Wk^T
__device__ float g_V[ROWS*DIM];        // ocean @ Wv^T
__device__ float g_attn[ROWS*DIM];     // attention output
__device__ float g_d2[ROWS*DIM];       // drift + attn@Wo^T
__device__ float g_y[ROWS*DIM];        // LN2
__device__ float g_h[ROWS*4*DIM];      // gelu(fc1)
__device__ float g_lam[NHEAD];

// ---------------- tf32 helpers ----------------
__device__ __forceinline__ unsigned f2tf32(float x) {
    unsigned u;
    asm("cvt.rna.tf32.f32 %0, %1;" : "=r"(u) : "f"(x));
    return u;
}

// D(16x8) += A(16x8) * B(8x8), tf32, fp32 accum.
__device__ __forceinline__ void mma_tf32(float* c, unsigned a0, unsigned a1,
                                         unsigned a2, unsigned a3,
                                         unsigned b0, unsigned b1) {
    asm volatile(
        "mma.sync.aligned.m16n8k8.row.col.f32.tf32.tf32.f32 "
        "{%0,%1,%2,%3}, {%4,%5,%6,%7}, {%8,%9}, {%0,%1,%2,%3};\n"
        : "+f"(c[0]), "+f"(c[1]), "+f"(c[2]), "+f"(c[3])
        : "r"(a0), "r"(a1), "r"(a2), "r"(a3), "r"(b0), "r"(b1));
}

// ---------------- LayerNorm: one warp per 256-elem row ----------------
__global__ __launch_bounds__(256) void ln_kernel(const float* __restrict__ in,
                                                 const float* __restrict__ gamma,
                                                 const float* __restrict__ beta,
                                                 float* __restrict__ out) {
    int warp = threadIdx.x >> 5, lane = threadIdx.x & 31;
    size_t row = (size_t)blockIdx.x * 8 + warp;
    const float* p = in + row * DIM;
    float4 a = *(const float4*)(p + lane * 4);
    float4 b = *(const float4*)(p + 128 + lane * 4);
    float s  = a.x + a.y + a.z + a.w + b.x + b.y + b.z + b.w;
    float ss = a.x*a.x + a.y*a.y + a.z*a.z + a.w*a.w
             + b.x*b.x + b.y*b.y + b.z*b.z + b.w*b.w;
    #pragma unroll
    for (int m = 16; m; m >>= 1) {
        s  += __shfl_xor_sync(0xffffffffu, s,  m);
        ss += __shfl_xor_sync(0xffffffffu, ss, m);
    }
    float mean = s * (1.0f / DIM);
    float var  = ss * (1.0f / DIM) - mean * mean;
    float rinv = rsqrtf(var + EPSF);
    float4 g1 = *(const float4*)(gamma + lane * 4);
    float4 g2 = *(const float4*)(gamma + 128 + lane * 4);
    float4 b1 = *(const float4*)(beta + lane * 4);
    float4 b2 = *(const float4*)(beta + 128 + lane * 4);
    float4 o1, o2;
    o1.x = (a.x - mean) * rinv * g1.x + b1.x;
    o1.y = (a.y - mean) * rinv * g1.y + b1.y;
    o1.z = (a.z - mean) * rinv * g1.z + b1.z;
    o1.w = (a.w - mean) * rinv * g1.w + b1.w;
    o2.x = (b.x - mean) * rinv * g2.x + b2.x;
    o2.y = (b.y - mean) * rinv * g2.y + b2.y;
    o2.z = (b.z - mean) * rinv * g2.z + b2.z;
    o2.w = (b.w - mean) * rinv * g2.w + b2.w;
    *(float4*)(out + row * DIM + lane * 4) = o1;
    *(float4*)(out + row * DIM + 128 + lane * 4) = o2;
}

// ---------------- lambda per head ----------------
__global__ void lam_kernel(const float* __restrict__ lq1, const float* __restrict__ lk1,
                           const float* __restrict__ lq2, const float* __restrict__ lk2) {
    int h = threadIdx.x >> 5, lane = threadIdx.x & 31;
    float a = lq1[h * HD + lane] * lk1[h * HD + lane];
    float b = lq2[h * HD + lane] * lk2[h * HD + lane];
    #pragma unroll
    for (int m = 16; m; m >>= 1) {
        a += __shfl_xor_sync(0xffffffffu, a, m);
        b += __shfl_xor_sync(0xffffffffu, b, m);
    }
    if (lane == 0) g_lam[h] = expf(a) - expf(b) + LAMBDA_INIT;
}

// ---------------- tensor-core GEMM v2: C[M,N] = A[M,K] @ B[N,K]^T ----------------
// 64x64 block tile, 256 threads, 8 warps each 16x32. BK=16 double-buffered,
// smem stride 20 -> conflict-free fragment loads.
template<bool BIAS, bool RES, bool GELU>
__global__ __launch_bounds__(256) void gemm_tc(const float* __restrict__ A,
                                               const float* __restrict__ Bm,
                                               const float* __restrict__ bias,
                                               const float* __restrict__ res,
                                               float* __restrict__ C,
                                               int M, int N, int K) {
    __shared__ unsigned As[2][64 * 20];
    __shared__ unsigned Bs[2][64 * 20];
    int tid = threadIdx.x;
    int m0 = blockIdx.y * 64, n0 = blockIdx.x * 64;
    int w = tid >> 5, lane = tid & 31;
    int wm = w >> 1, wn = w & 1;
    int grp = lane >> 2, tg = lane & 3;

    float c[4][4] = {};

    int lr = tid >> 2;          // 0..63
    int lc = (tid & 3) * 4;     // 0,4,8,12
    const float* Ap = A + (size_t)(m0 + lr) * K + lc;
    const float* Bp = Bm + (size_t)(n0 + lr) * K + lc;

    {
        float4 av = *(const float4*)(Ap);
        float4 bv = *(const float4*)(Bp);
        unsigned* da = &As[0][lr * 20 + lc];
        da[0] = f2tf32(av.x); da[1] = f2tf32(av.y); da[2] = f2tf32(av.z); da[3] = f2tf32(av.w);
        unsigned* db = &Bs[0][lr * 20 + lc];
        db[0] = f2tf32(bv.x); db[1] = f2tf32(bv.y); db[2] = f2tf32(bv.z); db[3] = f2tf32(bv.w);
    }
    __syncthreads();

    int nk = K / 16;
    for (int ks = 0; ks < nk; ks++) {
        int buf = ks & 1;
        if (ks + 1 < nk) {
            int k0 = (ks + 1) * 16;
            float4 av = *(const float4*)(Ap + k0);
            float4 bv = *(const float4*)(Bp + k0);
            unsigned* da = &As[buf ^ 1][lr * 20 + lc];
            da[0] = f2tf32(av.x); da[1] = f2tf32(av.y); da[2] = f2tf32(av.z); da[3] = f2tf32(av.w);
            unsigned* db = &Bs[buf ^ 1][lr * 20 + lc];
            db[0] = f2tf32(bv.x); db[1] = f2tf32(bv.y); db[2] = f2tf32(bv.z); db[3] = f2tf32(bv.w);
        }
        #pragma unroll
        for (int k8 = 0; k8 < 16; k8 += 8) {
            int rb = wm * 16;
            unsigned a0 = As[buf][(rb + grp) * 20 + k8 + tg];
            unsigned a1 = As[buf][(rb + grp + 8) * 20 + k8 + tg];
            unsigned a2 = As[buf][(rb + grp) * 20 + k8 + tg + 4];
            unsigned a3 = As[buf][(rb + grp + 8) * 20 + k8 + tg + 4];
            #pragma unroll
            for (int nt = 0; nt < 4; nt++) {
                int nb = wn * 32 + nt * 8;
                unsigned b0 = Bs[buf][(nb + grp) * 20 + k8 + tg];
                unsigned b1 = Bs[buf][(nb + grp) * 20 + k8 + tg + 4];
                mma_tf32(c[nt], a0, a1, a2, a3, b0, b1);
            }
        }
        __syncthreads();
    }

    #pragma unroll
    for (int nt = 0; nt < 4; nt++) {
        int mrow = m0 + wm * 16 + grp;
        int ncol = n0 + wn * 32 + nt * 8 + 2 * tg;
        #pragma unroll
        for (int half = 0; half < 2; half++) {
            int r = mrow + half * 8;
            float x0 = c[nt][half * 2 + 0];
            float x1 = c[nt][half * 2 + 1];
            if (BIAS) {
                const float2 bb = *(const float2*)(bias + ncol);
                x0 += bb.x; x1 += bb.y;
            }
            if (GELU) {
                x0 = 0.5f * x0 * (1.0f + erff(x0 * 0.7071067811865476f));
                x1 = 0.5f * x1 * (1.0f + erff(x1 * 0.7071067811865476f));
            }
            if (RES) {
                const float2 rr = *(const float2*)(res + (size_t)r * N + ncol);
                x0 += rr.x; x1 += rr.y;
            }
            float2 v; v.x = x0; v.y = x1;
            *(float2*)(C + (size_t)r * N + ncol) = v;
        }
    }
}

// ---------------- tensor-core two-stream flash differential attention v3 ----------------
// v2 + double-buffered K/V smem: ONE __syncthreads per 32-key tile (was 2).
// Stores target buf^1 while mma reads buf; the single end-of-iter barrier
// orders buf-reads(t) before buf-stores(t+1) and buf^1-stores(t) before
// buf^1-reads(t+1).
__global__ __launch_bounds__(256) void attn_tc(float* __restrict__ out) {
    __shared__ unsigned Ks[2][2][32 * 36];   // [buf][stream][key][d]  stride 36
    __shared__ unsigned Vt[2][32 * 36];      // [buf][d][key]          stride 36
    __shared__ unsigned Ps[2][64 * 36];      // [stream][row][key] (also Q staging / combine staging)

    int qb = blockIdx.x * 64, h = blockIdx.y, b = blockIdx.z;
    int tid = threadIdx.x;
    int w = tid >> 5, lane = tid & 31;
    int s = w >> 2, wq = w & 3;
    int grp = lane >> 2, tg = lane & 3;
    int rb = wq * 16;

    float lam = g_lam[h];
    const float* Qbase = g_Q + ((size_t)(b * ND) + qb) * 512 + h * 64;
    const float* Kbase = g_K + (size_t)(b * NOC) * 512 + h * 64;
    const float* Vbase = g_V + (size_t)(b * NOC) * 256 + h * 32;

    // ---- stage Q (scaled) into Ps, then hoist fragments to registers ----
    for (int idx = tid; idx < 64 * 64; idx += 256) {
        int r = idx >> 6, cc = idx & 63;
        Ps[cc >> 5][r * 36 + (cc & 31)] = f2tf32(SCALEF * Qbase[(size_t)r * 512 + cc]);
    }
    __syncthreads();
    unsigned qa[4][4];
    #pragma unroll
    for (int kd = 0; kd < 4; kd++) {
        int k8 = kd * 8;
        qa[kd][0] = Ps[s][(rb + grp) * 36 + k8 + tg];
        qa[kd][1] = Ps[s][(rb + grp + 8) * 36 + k8 + tg];
        qa[kd][2] = Ps[s][(rb + grp) * 36 + k8 + tg + 4];
        qa[kd][3] = Ps[s][(rb + grp + 8) * 36 + k8 + tg + 4];
    }

    // ---- load tile 0 into registers, then smem buf 0 ----
    float rK[8], rV[4];
    #pragma unroll
    for (int i = 0; i < 8; i++) {
        int idx = tid + i * 256;             // 32 keys x 64 cols
        int kk = idx >> 6, cc = idx & 63;
        rK[i] = Kbase[(size_t)kk * 512 + cc];
    }
    #pragma unroll
    for (int i = 0; i < 4; i++) {
        int idx = tid + i * 256;             // 32 keys x 32 d
        int kk = idx >> 5, d = idx & 31;
        rV[i] = Vbase[(size_t)kk * 256 + d];
    }
    __syncthreads();   // Q fragment extraction complete before Ps reused
    #pragma unroll
    for (int i = 0; i < 8; i++) {
        int idx = tid + i * 256;
        int kk = idx >> 6, cc = idx & 63;
        Ks[0][cc >> 5][kk * 36 + (cc & 31)] = f2tf32(rK[i]);
    }
    #pragma unroll
    for (int i = 0; i < 4; i++) {
        int idx = tid + i * 256;
        int kk = idx >> 5, d = idx & 31;
        Vt[0][d * 36 + kk] = f2tf32(rV[i]);
    }
    __syncthreads();

    float mrow[2] = {-1e30f, -1e30f};
    float lrow[2] = {0.0f, 0.0f};
    float o[4][4] = {};

    for (int t = 0; t < 64; t++) {
        int buf = t & 1;
        // issue prefetch for next tile (latency hidden by compute below)
        if (t < 63) {
            const float* Kb = Kbase + (size_t)(t + 1) * 32 * 512;
            const float* Vb = Vbase + (size_t)(t + 1) * 32 * 256;
            #pragma unroll
            for (int i = 0; i < 8; i++) {
                int idx = tid + i * 256;
                int kk = idx >> 6, cc = idx & 63;
                rK[i] = Kb[(size_t)kk * 512 + cc];
            }
            #pragma unroll
            for (int i = 0; i < 4; i++) {
                int idx = tid + i * 256;
                int kk = idx >> 5, d = idx & 31;
                rV[i] = Vb[(size_t)kk * 256 + d];
            }
        }

        // ---- S = Q K^T  (16 q x 32 keys per warp) ----
        float sc[4][4] = {};
        #pragma unroll
        for (int kd = 0; kd < 4; kd++) {
            int k8 = kd * 8;
            #pragma unroll
            for (int nt = 0; nt < 4; nt++) {
                unsigned b0 = Ks[buf][s][(nt * 8 + grp) * 36 + k8 + tg];
                unsigned b1 = Ks[buf][s][(nt * 8 + grp) * 36 + k8 + tg + 4];
                mma_tf32(sc[nt], qa[kd][0], qa[kd][1], qa[kd][2], qa[kd][3], b0, b1);
            }
        }

        // ---- online softmax ----
        float mx0 = fmaxf(fmaxf(sc[0][0], sc[0][1]), fmaxf(sc[1][0], sc[1][1]));
        mx0 = fmaxf(mx0, fmaxf(fmaxf(sc[2][0], sc[2][1]), fmaxf(sc[3][0], sc[3][1])));
        float mx1 = fmaxf(fmaxf(sc[0][2], sc[0][3]), fmaxf(sc[1][2], sc[1][3]));
        mx1 = fmaxf(mx1, fmaxf(fmaxf(sc[2][2], sc[2][3]), fmaxf(sc[3][2], sc[3][3])));
        mx0 = fmaxf(mx0, __shfl_xor_sync(0xffffffffu, mx0, 1));
        mx0 = fmaxf(mx0, __shfl_xor_sync(0xffffffffu, mx0, 2));
        mx1 = fmaxf(mx1, __shfl_xor_sync(0xffffffffu, mx1, 1));
        mx1 = fmaxf(mx1, __shfl_xor_sync(0xffffffffu, mx1, 2));
        float nm0 = fmaxf(mrow[0], mx0), nm1 = fmaxf(mrow[1], mx1);
        float cr0 = __expf(mrow[0] - nm0), cr1 = __expf(mrow[1] - nm1);
        mrow[0] = nm0; mrow[1] = nm1;
        float p[4][4];
        #pragma unroll
        for (int nt = 0; nt < 4; nt++) {
            p[nt][0] = __expf(sc[nt][0] - nm0);
            p[nt][1] = __expf(sc[nt][1] - nm0);
            p[nt][2] = __expf(sc[nt][2] - nm1);
            p[nt][3] = __expf(sc[nt][3] - nm1);
        }
        float ts0 = (p[0][0] + p[0][1]) + (p[1][0] + p[1][1])
                  + (p[2][0] + p[2][1]) + (p[3][0] + p[3][1]);
        float ts1 = (p[0][2] + p[0][3]) + (p[1][2] + p[1][3])
                  + (p[2][2] + p[2][3]) + (p[3][2] + p[3][3]);
        ts0 += __shfl_xor_sync(0xffffffffu, ts0, 1);
        ts0 += __shfl_xor_sync(0xffffffffu, ts0, 2);
        ts1 += __shfl_xor_sync(0xffffffffu, ts1, 1);
        ts1 += __shfl_xor_sync(0xffffffffu, ts1, 2);
        lrow[0] = lrow[0] * cr0 + ts0;
        lrow[1] = lrow[1] * cr1 + ts1;
        #pragma unroll
        for (int nt = 0; nt < 4; nt++) {
            o[nt][0] *= cr0; o[nt][1] *= cr0;
            o[nt][2] *= cr1; o[nt][3] *= cr1;
        }

        // ---- stage P (warp-local rows) ----
        #pragma unroll
        for (int nt = 0; nt < 4; nt++) {
            int col = nt * 8 + 2 * tg;
            Ps[s][(rb + grp) * 36 + col]         = f2tf32(p[nt][0]);
            Ps[s][(rb + grp) * 36 + col + 1]     = f2tf32(p[nt][1]);
            Ps[s][(rb + grp + 8) * 36 + col]     = f2tf32(p[nt][2]);
            Ps[s][(rb + grp + 8) * 36 + col + 1] = f2tf32(p[nt][3]);
        }
        __syncwarp();

        // ---- O += P V  (16 q x 32 d per warp, k=32 keys) ----
        #pragma unroll
        for (int kk8 = 0; kk8 < 32; kk8 += 8) {
            unsigned a0 = Ps[s][(rb + grp) * 36 + kk8 + tg];
            unsigned a1 = Ps[s][(rb + grp + 8) * 36 + kk8 + tg];
            unsigned a2 = Ps[s][(rb + grp) * 36 + kk8 + tg + 4];
            unsigned a3 = Ps[s][(rb + grp + 8) * 36 + kk8 + tg + 4];
            #pragma unroll
            for (int nt = 0; nt < 4; nt++) {
                unsigned b0 = Vt[buf][(nt * 8 + grp) * 36 + kk8 + tg];
                unsigned b1 = Vt[buf][(nt * 8 + grp) * 36 + kk8 + tg + 4];
                mma_tf32(o[nt], a0, a1, a2, a3, b0, b1);
            }
        }

        // ---- store prefetched tile into the OTHER buffer (no read conflict) ----
        if (t < 63) {
            #pragma unroll
            for (int i = 0; i < 8; i++) {
                int idx = tid + i * 256;
                int kk = idx >> 6, cc = idx & 63;
                Ks[buf ^ 1][cc >> 5][kk * 36 + (cc & 31)] = f2tf32(rK[i]);
            }
            #pragma unroll
            for (int i = 0; i < 4; i++) {
                int idx = tid + i * 256;
                int kk = idx >> 5, d = idx & 31;
                Vt[buf ^ 1][d * 36 + kk] = f2tf32(rV[i]);
            }
        }
        __syncthreads();   // single barrier: orders buf reads (this iter) vs
                           // buf stores (next iter), and buf^1 stores vs reads
    }

    // ---- combine: out = O1/l1 - lam*O2/l2  (stream2 -> Ps[0], stream1 reads) ----
    float inv0 = 1.0f / lrow[0], inv1 = 1.0f / lrow[1];
    float* Osm = (float*)&Ps[0][0];   // 64 x 32, stride 36
    if (s == 1) {
        #pragma unroll
        for (int nt = 0; nt < 4; nt++) {
            int col = nt * 8 + 2 * tg;
            Osm[(rb + grp) * 36 + col]         = o[nt][0] * inv0 * lam;
            Osm[(rb + grp) * 36 + col + 1]     = o[nt][1] * inv0 * lam;
            Osm[(rb + grp + 8) * 36 + col]     = o[nt][2] * inv1 * lam;
            Osm[(rb + grp + 8) * 36 + col + 1] = o[nt][3] * inv1 * lam;
        }
    }
    __syncthreads();
    if (s == 0) {
        float* Obase = out + ((size_t)(b * ND) + qb) * 256 + h * 32;
        #pragma unroll
        for (int nt = 0; nt < 4; nt++) {
            int col = nt * 8 + 2 * tg;
            float2 v0, v1;
            v0.x = o[nt][0] * inv0 - Osm[(rb + grp) * 36 + col];
            v0.y = o[nt][1] * inv0 - Osm[(rb + grp) * 36 + col + 1];
            v1.x = o[nt][2] * inv1 - Osm[(rb + grp + 8) * 36 + col];
            v1.y = o[nt][3] * inv1 - Osm[(rb + grp + 8) * 36 + col + 1];
            *(float2*)(Obase + (size_t)(rb + grp) * 256 + col) = v0;
            *(float2*)(Obase + (size_t)(rb + grp + 8) * 256 + col) = v1;
        }
    }
}

// ---------------- ocean passthrough ----------------
__global__ void copy_kernel(const float4* __restrict__ in, float4* __restrict__ out, int n4) {
    int i = blockIdx.x * blockDim.x + threadIdx.x;
    if (i < n4) out[i] = in[i];
}

// ---------------- host ----------------
static float* symaddr(const void* sym) {
    void* p = nullptr;
    cudaGetSymbolAddress(&p, sym);
    return (float*)p;
}

extern "C" void kernel_launch(void* const* d_in, const int* in_sizes, int n_in,
                              void* d_out, int out_size) {
    const float* drift = (const float*)d_in[0];
    const float* ocean = (const float*)d_in[1];
    const float* Wq    = (const float*)d_in[2];
    const float* Wk    = (const float*)d_in[3];
    const float* Wv    = (const float*)d_in[4];
    const float* Wo    = (const float*)d_in[5];
    const float* lq1   = (const float*)d_in[6];
    const float* lk1   = (const float*)d_in[7];
    const float* lq2   = (const float*)d_in[8];
    const float* lk2   = (const float*)d_in[9];
    const float* gamma = (const float*)d_in[10];
    const float* beta  = (const float*)d_in[11];
    const float* fc1w  = (const float*)d_in[12];
    const float* fc1b  = (const float*)d_in[13];
    const float* fc2w  = (const float*)d_in[14];
    const float* fc2b  = (const float*)d_in[15];
    float* out = (float*)d_out;

    float* px    = symaddr(g_x);
    float* pQ    = symaddr(g_Q);
    float* pK    = symaddr(g_K);
    float* pV    = symaddr(g_V);
    float* pAttn = symaddr(g_attn);
    float* pD2   = symaddr(g_d2);
    float* pY    = symaddr(g_y);
    float* pH    = symaddr(g_h);

    // 1. x = LN(drift)
    ln_kernel<<<ROWS / 8, 256>>>(drift, gamma, beta, px);
    // 2. lambda
    lam_kernel<<<1, 256>>>(lq1, lk1, lq2, lk2);
    // 3-5. Q, K, V projections (tf32 tensor cores, 64x64 tiles)
    gemm_tc<false, false, false><<<dim3(512 / 64, ROWS / 64), 256>>>(px, Wq, nullptr, nullptr, pQ, ROWS, 512, 256);
    gemm_tc<false, false, false><<<dim3(512 / 64, ROWS / 64), 256>>>(ocean, Wk, nullptr, nullptr, pK, ROWS, 512, 256);
    gemm_tc<false, false, false><<<dim3(256 / 64, ROWS / 64), 256>>>(ocean, Wv, nullptr, nullptr, pV, ROWS, 256, 256);
    // 6. differential flash attention (tf32 tensor cores, v3 double-buffered)
    attn_tc<<<dim3(ND / 64, NHEAD, BATCH), 256>>>(pAttn);
    // 7. drift2 = drift + attn @ Wo^T
    gemm_tc<false, true, false><<<dim3(256 / 64, ROWS / 64), 256>>>(pAttn, Wo, nullptr, drift, pD2, ROWS, 256, 256);
    // 8. y = LN(drift2)
    ln_kernel<<<ROWS / 8, 256>>>(pD2, gamma, beta, pY);
    // 9. h = gelu(y @ fc1^T + b1)
    gemm_tc<true, false, true><<<dim3(1024 / 64, ROWS / 64), 256>>>(pY, fc1w, fc1b, nullptr, pH, ROWS, 1024, 256);
    // 10. out_drift = drift2 + h @ fc2^T + b2
    gemm_tc<true, true, false><<<dim3(256 / 64, ROWS / 64), 256>>>(pH, fc2w, fc2b, pD2, out, ROWS, 256, 1024);
    // 11. ocean passthrough
    copy_kernel<<<(ROWS * DIM / 4 + 255) / 256, 256>>>((const float4*)ocean,
                                                       (float4*)(out + (size_t)ROWS * DIM),
                                                       ROWS * DIM / 4);
}